// round 9
// baseline (speedup 1.0000x reference)
#include <cuda_runtime.h>

#define NN 100000
#define NE 1600000
#define CH 64
#define NB_SCAN 98   // ceil(NN/1024)

// Device scratch (no allocs allowed)
__device__ float g_agg[(size_t)NN * CH];     // h = x + segment_sum
__device__ int   g_cnt[NN];                  // histogram, then write cursors
__device__ int   g_off[NN];                  // exclusive offsets
__device__ int   g_blksum[128];              // scan block sums
__device__ int   g_srt[NE];                  // src ids sorted by dst
__device__ int   g_idx_is64;

// ---------------------------------------------------------------------------
// Kernel 0: detect int64-vs-int32 edge_index (JAX x64-off narrows to int32).
// ---------------------------------------------------------------------------
__global__ void detect_k(const unsigned long long* __restrict__ ei) {
    if (threadIdx.x == 0 && blockIdx.x == 0) {
        int is64 = 1;
        for (int i = 0; i < 64; i++)
            if (ei[i] >= (unsigned long long)NN) { is64 = 0; break; }
        g_idx_is64 = is64;
    }
}

__device__ __forceinline__ int load_idx(const void* eiv, long long pos) {
    if (g_idx_is64) return (int)__ldg(&((const long long*)eiv)[pos]);
    return __ldg(&((const int*)eiv)[pos]);
}

// ---------------------------------------------------------------------------
// Sort pipeline: zero -> histogram -> block scan -> top scan -> add -> reorder
// ---------------------------------------------------------------------------
__global__ void zero_k() {
    int i = blockIdx.x * blockDim.x + threadIdx.x;
    if (i < NN) g_cnt[i] = 0;
}

__global__ void hist_k(const void* __restrict__ eiv) {
    int e = blockIdx.x * blockDim.x + threadIdx.x;
    if (e >= NE) return;
    int dst = load_idx(eiv, (long long)NE + e);
    atomicAdd(&g_cnt[dst], 1);
}

__global__ void __launch_bounds__(1024) scan_block_k() {
    __shared__ int warp_sums[32];
    const int tid = threadIdx.x;
    const int i = blockIdx.x * 1024 + tid;
    const int lane = tid & 31, warp = tid >> 5;
    int c = (i < NN) ? g_cnt[i] : 0;
    int v = c;
    #pragma unroll
    for (int d = 1; d < 32; d <<= 1) {
        int u = __shfl_up_sync(0xffffffffu, v, d);
        if (lane >= d) v += u;
    }
    if (lane == 31) warp_sums[warp] = v;
    __syncthreads();
    if (tid < 32) {
        int w = warp_sums[tid];
        #pragma unroll
        for (int d = 1; d < 32; d <<= 1) {
            int u = __shfl_up_sync(0xffffffffu, w, d);
            if (tid >= d) w += u;
        }
        warp_sums[tid] = w;  // inclusive per-warp totals
    }
    __syncthreads();
    const int wpref = warp ? warp_sums[warp - 1] : 0;
    if (i < NN) g_off[i] = wpref + v - c;      // exclusive within block
    if (tid == 1023) g_blksum[blockIdx.x] = wpref + v;
}

__global__ void scan_top_k() {   // 1 block, 128 threads over NB_SCAN sums
    __shared__ int ws[4];
    const int tid = threadIdx.x;
    const int lane = tid & 31, warp = tid >> 5;
    int c = (tid < NB_SCAN) ? g_blksum[tid] : 0;
    int v = c;
    #pragma unroll
    for (int d = 1; d < 32; d <<= 1) {
        int u = __shfl_up_sync(0xffffffffu, v, d);
        if (lane >= d) v += u;
    }
    if (lane == 31) ws[warp] = v;
    __syncthreads();
    if (tid == 0) {
        int s = 0;
        #pragma unroll
        for (int w = 0; w < 4; w++) { int t = ws[w]; ws[w] = s; s += t; }
    }
    __syncthreads();
    if (tid < NB_SCAN) g_blksum[tid] = ws[warp] + v - c;   // exclusive
}

__global__ void scan_add_k() {
    int i = blockIdx.x * blockDim.x + threadIdx.x;
    if (i < NN) {
        int o = g_off[i] + g_blksum[i >> 10];
        g_off[i] = o;
        g_cnt[i] = o;    // running cursor for reorder
    }
}

__global__ void reorder_k(const void* __restrict__ eiv) {
    int e = blockIdx.x * blockDim.x + threadIdx.x;
    if (e >= NE) return;
    int src = load_idx(eiv, e);
    int dst = load_idx(eiv, (long long)NE + e);
    int pos = atomicAdd(&g_cnt[dst], 1);
    g_srt[pos] = src;
}

// ---------------------------------------------------------------------------
// Aggregation: one warp per node, float2 per lane. Reads sorted src list,
// accumulates in registers, writes the 256B row ONCE (no atomics).
// ---------------------------------------------------------------------------
__global__ void __launch_bounds__(256) agg_k(const float2* __restrict__ x2) {
    const int gwarp = (blockIdx.x * 256 + threadIdx.x) >> 5;
    if (gwarp >= NN) return;
    const int lane = threadIdx.x & 31;
    const int off0 = __ldg(&g_off[gwarp]);
    const int off1 = (gwarp + 1 < NN) ? __ldg(&g_off[gwarp + 1]) : NE;

    float2 acc = x2[(size_t)gwarp * 32 + lane];   // self term (eps=0 GIN)
    int j = off0;
    for (; j + 4 <= off1; j += 4) {
        int s0 = __ldg(&g_srt[j + 0]);
        int s1 = __ldg(&g_srt[j + 1]);
        int s2 = __ldg(&g_srt[j + 2]);
        int s3 = __ldg(&g_srt[j + 3]);
        float2 v0 = x2[(size_t)s0 * 32 + lane];
        float2 v1 = x2[(size_t)s1 * 32 + lane];
        float2 v2 = x2[(size_t)s2 * 32 + lane];
        float2 v3 = x2[(size_t)s3 * 32 + lane];
        acc.x += (v0.x + v1.x) + (v2.x + v3.x);
        acc.y += (v0.y + v1.y) + (v2.y + v3.y);
    }
    for (; j < off1; j++) {
        int s = __ldg(&g_srt[j]);
        float2 v = x2[(size_t)s * 32 + lane];
        acc.x += v.x; acc.y += v.y;
    }
    *reinterpret_cast<float2*>(g_agg + (size_t)gwarp * CH + lane * 2) = acc;
}

// ---------------------------------------------------------------------------
// MLP via tf32 mma.sync (m16n8k8), fp32 accumulate.
// Block 256 = 8 warps; tile 128 nodes x 64 ch; warp owns rows w*16..w*16+15,
// so the whole tile loop is warp-private (only __syncwarp).
// Weights pre-packed in smem in B-fragment order -> one LDS.64 per frag.
// Activations in smem, stride 68 floats -> A-frag scalar LDS conflict-free.
// ---------------------------------------------------------------------------
#define MT 128
#define MLP_TPB 256
#define MLP_SMEM_FLOATS (4096 + 4096 + 64 + 64 + 128 * 68)

__device__ __forceinline__ unsigned f2tf32(float f) {
    unsigned u;
    asm("cvt.rna.tf32.f32 %0, %1;" : "=r"(u) : "f"(f));
    return u;
}

__device__ __forceinline__ void mma_tf32(float c[4],
                                         unsigned a0, unsigned a1,
                                         unsigned a2, unsigned a3,
                                         unsigned b0, unsigned b1) {
    asm("mma.sync.aligned.m16n8k8.row.col.f32.tf32.tf32.f32 "
        "{%0,%1,%2,%3}, {%4,%5,%6,%7}, {%8,%9}, {%0,%1,%2,%3};"
        : "+f"(c[0]), "+f"(c[1]), "+f"(c[2]), "+f"(c[3])
        : "r"(a0), "r"(a1), "r"(a2), "r"(a3), "r"(b0), "r"(b1));
}

__global__ void __launch_bounds__(MLP_TPB)
mlp_tc_k(const float* __restrict__ W1, const float* __restrict__ b1,
         const float* __restrict__ W2, const float* __restrict__ b2,
         const float* __restrict__ alpha, float* __restrict__ out,
         int out_size) {
    extern __shared__ float smem[];
    unsigned* wp1 = reinterpret_cast<unsigned*>(smem);        // 4096
    unsigned* wp2 = wp1 + 4096;                               // 4096
    float* sb1 = smem + 8192;                                 // 64
    float* sb2 = sb1 + 64;                                    // 64
    unsigned* hs = reinterpret_cast<unsigned*>(sb2 + 64);     // 128 x 68

    const int tid = threadIdx.x;
    // Pack weights into exact B-fragment order:
    //   wp[(((ks*8+nt)*32 + lane)*2 + r] = tf32(W[ks*8 + lane%4 + 4r][nt*8 + lane/4])
    for (int i = tid; i < 4096; i += MLP_TPB) {
        const int r  = i & 1;
        const int l  = (i >> 1) & 31;
        const int nt = (i >> 6) & 7;
        const int ks = i >> 9;
        const int k = ks * 8 + (l & 3) + r * 4;
        const int n = nt * 8 + (l >> 2);
        wp1[i] = f2tf32(W1[k * 64 + n]);
        wp2[i] = f2tf32(W2[k * 64 + n]);
    }
    if (tid < 64) { sb1[tid] = b1[tid]; sb2[tid] = b2[tid]; }
    const float gate = 1.0f / (1.0f + expf(-alpha[0]));
    __syncthreads();

    const int warp = tid >> 5, lane = tid & 31;
    const int g = lane >> 2, tg = lane & 3;
    const int wrow = warp * 16;
    const int r0 = wrow + g;      // A-frag rows
    const int r1 = r0 + 8;

    for (int base = blockIdx.x * MT; base < NN; base += gridDim.x * MT) {
        // ---- load my warp's 16 rows (tf32-converted) ----
        #pragma unroll
        for (int i = 0; i < 8; i++) {
            const int ii = i * 32 + lane;
            const int row = ii >> 4, c4 = (ii & 15) * 4;
            const int node = base + wrow + row;
            float4 v = make_float4(0.f, 0.f, 0.f, 0.f);
            if (node < NN)
                v = *reinterpret_cast<const float4*>(
                        g_agg + (size_t)node * 64 + c4);
            unsigned* p = &hs[(wrow + row) * 68 + c4];
            p[0] = f2tf32(v.x); p[1] = f2tf32(v.y);
            p[2] = f2tf32(v.z); p[3] = f2tf32(v.w);
        }
        __syncwarp();

        float c[8][4];
        #pragma unroll
        for (int nt = 0; nt < 8; nt++)
            c[nt][0] = c[nt][1] = c[nt][2] = c[nt][3] = 0.f;

        // ---- layer 1 ----
        #pragma unroll
        for (int ks = 0; ks < 8; ks++) {
            const unsigned a0 = hs[r0 * 68 + ks * 8 + tg];
            const unsigned a1 = hs[r1 * 68 + ks * 8 + tg];
            const unsigned a2 = hs[r0 * 68 + ks * 8 + tg + 4];
            const unsigned a3 = hs[r1 * 68 + ks * 8 + tg + 4];
            #pragma unroll
            for (int nt = 0; nt < 8; nt++) {
                const uint2 b = *reinterpret_cast<const uint2*>(
                    &wp1[((ks * 8 + nt) * 32 + lane) * 2]);
                mma_tf32(c[nt], a0, a1, a2, a3, b.x, b.y);
            }
        }
        __syncwarp();

        // ---- epilogue 1: bias + relu, back into hs (warp-private rows) ----
        #pragma unroll
        for (int nt = 0; nt < 8; nt++) {
            const int col = nt * 8 + tg * 2;
            hs[r0 * 68 + col    ] = f2tf32(fmaxf(c[nt][0] + sb1[col    ], 0.f));
            hs[r0 * 68 + col + 1] = f2tf32(fmaxf(c[nt][1] + sb1[col + 1], 0.f));
            hs[r1 * 68 + col    ] = f2tf32(fmaxf(c[nt][2] + sb1[col    ], 0.f));
            hs[r1 * 68 + col + 1] = f2tf32(fmaxf(c[nt][3] + sb1[col + 1], 0.f));
        }
        __syncwarp();

        #pragma unroll
        for (int nt = 0; nt < 8; nt++)
            c[nt][0] = c[nt][1] = c[nt][2] = c[nt][3] = 0.f;

        // ---- layer 2 ----
        #pragma unroll
        for (int ks = 0; ks < 8; ks++) {
            const unsigned a0 = hs[r0 * 68 + ks * 8 + tg];
            const unsigned a1 = hs[r1 * 68 + ks * 8 + tg];
            const unsigned a2 = hs[r0 * 68 + ks * 8 + tg + 4];
            const unsigned a3 = hs[r1 * 68 + ks * 8 + tg + 4];
            #pragma unroll
            for (int nt = 0; nt < 8; nt++) {
                const uint2 b = *reinterpret_cast<const uint2*>(
                    &wp2[((ks * 8 + nt) * 32 + lane) * 2]);
                mma_tf32(c[nt], a0, a1, a2, a3, b.x, b.y);
            }
        }

        // ---- epilogue 2: gate*(c+b2) -> global ----
        const int n0 = base + r0, n1 = base + r1;
        #pragma unroll
        for (int nt = 0; nt < 8; nt++) {
            const int col = nt * 8 + tg * 2;
            if (n0 < NN) {
                float2 o = make_float2(gate * (c[nt][0] + sb2[col]),
                                       gate * (c[nt][1] + sb2[col + 1]));
                *reinterpret_cast<float2*>(out + (size_t)n0 * 64 + col) = o;
            }
            if (n1 < NN) {
                float2 o = make_float2(gate * (c[nt][2] + sb2[col]),
                                       gate * (c[nt][3] + sb2[col + 1]));
                *reinterpret_cast<float2*>(out + (size_t)n1 * 64 + col) = o;
            }
        }
        __syncwarp();   // hs reads done before next tile overwrites
    }

    // Tail: reference also returns gate (flattened after main output).
    const int extra = out_size - NN * CH;
    if (blockIdx.x == 0 && tid < extra) out[NN * CH + tid] = gate;
}

// ---------------------------------------------------------------------------
extern "C" void kernel_launch(void* const* d_in, const int* in_sizes, int n_in,
                              void* d_out, int out_size) {
    const float* x     = (const float*)d_in[0];
    const void*  ei    = d_in[1];
    const float* W1    = (const float*)d_in[2];
    const float* b1    = (const float*)d_in[3];
    const float* W2    = (const float*)d_in[4];
    const float* b2    = (const float*)d_in[5];
    const float* alpha = (const float*)d_in[6];
    float*       out   = (float*)d_out;

    detect_k<<<1, 32>>>((const unsigned long long*)ei);

    zero_k<<<(NN + 255) / 256, 256>>>();
    hist_k<<<(NE + 255) / 256, 256>>>(ei);
    scan_block_k<<<NB_SCAN, 1024>>>();
    scan_top_k<<<1, 128>>>();
    scan_add_k<<<(NN + 255) / 256, 256>>>();
    reorder_k<<<(NE + 255) / 256, 256>>>(ei);

    agg_k<<<(NN * 32 + 255) / 256, 256>>>(
        reinterpret_cast<const float2*>(x));

    static const size_t smem_bytes = MLP_SMEM_FLOATS * sizeof(float);
    cudaFuncSetAttribute(mlp_tc_k, cudaFuncAttributeMaxDynamicSharedMemorySize,
                         (int)smem_bytes);
    mlp_tc_k<<<444, MLP_TPB, smem_bytes>>>(W1, b1, W2, b2, alpha, out, out_size);
}

// round 10
// speedup vs baseline: 1.0172x; 1.0172x over previous
#include <cuda_runtime.h>
#include <cuda_fp16.h>

#define NN 100000
#define NE 1600000
#define CH 64
#define NB_SCAN 98   // ceil(NN/1024)

// Device scratch (no allocs allowed)
__device__ float   g_agg[(size_t)NN * CH];   // h = x + segment_sum
__device__ __half2 g_xh[(size_t)NN * 32];    // fp16 mirror of x (gather table)
__device__ int     g_cnt[NN];                // histogram, then write cursors
__device__ int     g_off[NN];                // exclusive offsets
__device__ int     g_blksum[128];            // scan block sums
__device__ int     g_srt[NE];                // src ids sorted by dst
__device__ int     g_idx_is64;

// ---------------------------------------------------------------------------
// Kernel 0: detect int64-vs-int32 edge_index (JAX x64-off narrows to int32).
// ---------------------------------------------------------------------------
__global__ void detect_k(const unsigned long long* __restrict__ ei) {
    if (threadIdx.x == 0 && blockIdx.x == 0) {
        int is64 = 1;
        for (int i = 0; i < 64; i++)
            if (ei[i] >= (unsigned long long)NN) { is64 = 0; break; }
        g_idx_is64 = is64;
    }
}

__device__ __forceinline__ int load_idx(const void* eiv, long long pos) {
    if (g_idx_is64) return (int)__ldg(&((const long long*)eiv)[pos]);
    return __ldg(&((const int*)eiv)[pos]);
}

// ---------------------------------------------------------------------------
// Kernel: build fp16 mirror of x (halves agg gather bytes).
// ---------------------------------------------------------------------------
__global__ void tofp16_k(const float2* __restrict__ x2) {
    int i = blockIdx.x * blockDim.x + threadIdx.x;
    if (i < NN * 32) {
        float2 v = x2[i];
        g_xh[i] = __floats2half2_rn(v.x, v.y);
    }
}

// ---------------------------------------------------------------------------
// Sort pipeline: zero -> histogram -> block scan -> top scan -> add -> reorder
// ---------------------------------------------------------------------------
__global__ void zero_k() {
    int i = blockIdx.x * blockDim.x + threadIdx.x;
    if (i < NN) g_cnt[i] = 0;
}

__global__ void hist_k(const void* __restrict__ eiv) {
    int e = blockIdx.x * blockDim.x + threadIdx.x;
    if (e >= NE) return;
    int dst = load_idx(eiv, (long long)NE + e);
    atomicAdd(&g_cnt[dst], 1);
}

__global__ void __launch_bounds__(1024) scan_block_k() {
    __shared__ int warp_sums[32];
    const int tid = threadIdx.x;
    const int i = blockIdx.x * 1024 + tid;
    const int lane = tid & 31, warp = tid >> 5;
    int c = (i < NN) ? g_cnt[i] : 0;
    int v = c;
    #pragma unroll
    for (int d = 1; d < 32; d <<= 1) {
        int u = __shfl_up_sync(0xffffffffu, v, d);
        if (lane >= d) v += u;
    }
    if (lane == 31) warp_sums[warp] = v;
    __syncthreads();
    if (tid < 32) {
        int w = warp_sums[tid];
        #pragma unroll
        for (int d = 1; d < 32; d <<= 1) {
            int u = __shfl_up_sync(0xffffffffu, w, d);
            if (tid >= d) w += u;
        }
        warp_sums[tid] = w;  // inclusive per-warp totals
    }
    __syncthreads();
    const int wpref = warp ? warp_sums[warp - 1] : 0;
    if (i < NN) g_off[i] = wpref + v - c;      // exclusive within block
    if (tid == 1023) g_blksum[blockIdx.x] = wpref + v;
}

__global__ void scan_top_k() {   // 1 block, 128 threads over NB_SCAN sums
    __shared__ int ws[4];
    const int tid = threadIdx.x;
    const int lane = tid & 31, warp = tid >> 5;
    int c = (tid < NB_SCAN) ? g_blksum[tid] : 0;
    int v = c;
    #pragma unroll
    for (int d = 1; d < 32; d <<= 1) {
        int u = __shfl_up_sync(0xffffffffu, v, d);
        if (lane >= d) v += u;
    }
    if (lane == 31) ws[warp] = v;
    __syncthreads();
    if (tid == 0) {
        int s = 0;
        #pragma unroll
        for (int w = 0; w < 4; w++) { int t = ws[w]; ws[w] = s; s += t; }
    }
    __syncthreads();
    if (tid < NB_SCAN) g_blksum[tid] = ws[warp] + v - c;   // exclusive
}

__global__ void scan_add_k() {
    int i = blockIdx.x * blockDim.x + threadIdx.x;
    if (i < NN) {
        int o = g_off[i] + g_blksum[i >> 10];
        g_off[i] = o;
        g_cnt[i] = o;    // running cursor for reorder
    }
}

__global__ void reorder_k(const void* __restrict__ eiv) {
    int e = blockIdx.x * blockDim.x + threadIdx.x;
    if (e >= NE) return;
    int src = load_idx(eiv, e);
    int dst = load_idx(eiv, (long long)NE + e);
    int pos = atomicAdd(&g_cnt[dst], 1);
    g_srt[pos] = src;
}

// ---------------------------------------------------------------------------
// Aggregation: one warp per node. Self term from fp32 x; neighbor rows
// gathered from the fp16 mirror (128B/row), accumulated in fp32 registers,
// 256B result row written ONCE. No atomics.
// ---------------------------------------------------------------------------
__global__ void __launch_bounds__(256) agg_k(const float2* __restrict__ x2) {
    const int gwarp = (blockIdx.x * 256 + threadIdx.x) >> 5;
    if (gwarp >= NN) return;
    const int lane = threadIdx.x & 31;
    const int off0 = __ldg(&g_off[gwarp]);
    const int off1 = (gwarp + 1 < NN) ? __ldg(&g_off[gwarp + 1]) : NE;

    float2 acc = x2[(size_t)gwarp * 32 + lane];   // self term in fp32 (eps=0 GIN)
    int j = off0;
    for (; j + 4 <= off1; j += 4) {
        int s0 = __ldg(&g_srt[j + 0]);
        int s1 = __ldg(&g_srt[j + 1]);
        int s2 = __ldg(&g_srt[j + 2]);
        int s3 = __ldg(&g_srt[j + 3]);
        float2 v0 = __half22float2(g_xh[(size_t)s0 * 32 + lane]);
        float2 v1 = __half22float2(g_xh[(size_t)s1 * 32 + lane]);
        float2 v2 = __half22float2(g_xh[(size_t)s2 * 32 + lane]);
        float2 v3 = __half22float2(g_xh[(size_t)s3 * 32 + lane]);
        acc.x += (v0.x + v1.x) + (v2.x + v3.x);
        acc.y += (v0.y + v1.y) + (v2.y + v3.y);
    }
    for (; j < off1; j++) {
        int s = __ldg(&g_srt[j]);
        float2 v = __half22float2(g_xh[(size_t)s * 32 + lane]);
        acc.x += v.x; acc.y += v.y;
    }
    *reinterpret_cast<float2*>(g_agg + (size_t)gwarp * CH + lane * 2) = acc;
}

// ---------------------------------------------------------------------------
// Kernel 3: fused MLP + gate — register-blocked (proven 60.1us version).
// ---------------------------------------------------------------------------
#define NPT 64        // nodes per tile
#define RPT 4         // nodes per thread
#define TPB 256
#define HS_STRIDE 68

#define SMEM_FLOATS (2 * CH * CH + 2 * CH + NPT * HS_STRIDE)

__global__ void __launch_bounds__(TPB)
mlp_k(const float* __restrict__ W1, const float* __restrict__ b1,
      const float* __restrict__ W2, const float* __restrict__ b2,
      const float* __restrict__ alpha, float* __restrict__ out,
      int out_size) {
    extern __shared__ float smem[];
    float* sW1 = smem;                       // 4096
    float* sW2 = sW1 + CH * CH;              // 4096
    float* sb1 = sW2 + CH * CH;              // 64
    float* sb2 = sb1 + CH;                   // 64
    float* hs  = sb2 + CH;                   // 64 x 68

    const int tid = threadIdx.x;
    for (int i = tid; i < CH * CH; i += TPB) {
        sW1[i] = W1[i];
        sW2[i] = W2[i];
    }
    if (tid < CH) { sb1[tid] = b1[tid]; sb2[tid] = b2[tid]; }
    const float gate = 1.0f / (1.0f + expf(-alpha[0]));
    __syncthreads();

    const int t  = tid & 15;       // j-group
    const int r  = tid >> 4;       // node-group
    const int j4 = t * 4;
    const int nb = r * RPT;        // first node (within tile) for this thread

    for (int base = blockIdx.x * NPT; base < NN; base += gridDim.x * NPT) {
        // ---- load tile: hs[row][:] = g_agg[base+row][:]  (coalesced) ----
        for (int i = tid; i < NPT * 16; i += TPB) {
            const int row = i >> 4, g = i & 15;
            const int node = base + row;
            if (node < NN) {
                *reinterpret_cast<float4*>(&hs[row * HS_STRIDE + g * 4]) =
                    *reinterpret_cast<const float4*>(
                        g_agg + (size_t)node * CH + g * 4);
            }
        }
        __syncthreads();

        // ---- layer 1: acc = relu(h @ W1 + b1), result kept in regs ----
        float4 acc[RPT];
        {
            const float4 bb = *reinterpret_cast<const float4*>(&sb1[j4]);
            #pragma unroll
            for (int n = 0; n < RPT; n++) acc[n] = bb;
        }
        #pragma unroll
        for (int k = 0; k < CH; k += 4) {
            const float4 w0 = *reinterpret_cast<const float4*>(&sW1[(k + 0) * CH + j4]);
            const float4 w1 = *reinterpret_cast<const float4*>(&sW1[(k + 1) * CH + j4]);
            const float4 w2 = *reinterpret_cast<const float4*>(&sW1[(k + 2) * CH + j4]);
            const float4 w3 = *reinterpret_cast<const float4*>(&sW1[(k + 3) * CH + j4]);
            #pragma unroll
            for (int n = 0; n < RPT; n++) {
                const float4 a = *reinterpret_cast<const float4*>(
                    &hs[(nb + n) * HS_STRIDE + k]);
                acc[n].x += a.x * w0.x + a.y * w1.x + a.z * w2.x + a.w * w3.x;
                acc[n].y += a.x * w0.y + a.y * w1.y + a.z * w2.y + a.w * w3.y;
                acc[n].z += a.x * w0.z + a.y * w1.z + a.z * w2.z + a.w * w3.z;
                acc[n].w += a.x * w0.w + a.y * w1.w + a.z * w2.w + a.w * w3.w;
            }
        }
        __syncthreads();   // everyone done reading hs
        #pragma unroll
        for (int n = 0; n < RPT; n++) {
            float4 v = acc[n];
            v.x = fmaxf(v.x, 0.0f); v.y = fmaxf(v.y, 0.0f);
            v.z = fmaxf(v.z, 0.0f); v.w = fmaxf(v.w, 0.0f);
            *reinterpret_cast<float4*>(&hs[(nb + n) * HS_STRIDE + j4]) = v;
        }
        __syncthreads();

        // ---- layer 2: out = gate * (h1 @ W2 + b2) ----
        {
            const float4 bb = *reinterpret_cast<const float4*>(&sb2[j4]);
            #pragma unroll
            for (int n = 0; n < RPT; n++) acc[n] = bb;
        }
        #pragma unroll
        for (int k = 0; k < CH; k += 4) {
            const float4 w0 = *reinterpret_cast<const float4*>(&sW2[(k + 0) * CH + j4]);
            const float4 w1 = *reinterpret_cast<const float4*>(&sW2[(k + 1) * CH + j4]);
            const float4 w2 = *reinterpret_cast<const float4*>(&sW2[(k + 2) * CH + j4]);
            const float4 w3 = *reinterpret_cast<const float4*>(&sW2[(k + 3) * CH + j4]);
            #pragma unroll
            for (int n = 0; n < RPT; n++) {
                const float4 a = *reinterpret_cast<const float4*>(
                    &hs[(nb + n) * HS_STRIDE + k]);
                acc[n].x += a.x * w0.x + a.y * w1.x + a.z * w2.x + a.w * w3.x;
                acc[n].y += a.x * w0.y + a.y * w1.y + a.z * w2.y + a.w * w3.y;
                acc[n].z += a.x * w0.z + a.y * w1.z + a.z * w2.z + a.w * w3.z;
                acc[n].w += a.x * w0.w + a.y * w1.w + a.z * w2.w + a.w * w3.w;
            }
        }
        #pragma unroll
        for (int n = 0; n < RPT; n++) {
            const int node = base + nb + n;
            if (node < NN) {
                float4 o = make_float4(gate * acc[n].x, gate * acc[n].y,
                                       gate * acc[n].z, gate * acc[n].w);
                *reinterpret_cast<float4*>(out + (size_t)node * CH + j4) = o;
            }
        }
        __syncthreads();   // protect hs before next tile
    }

    // Tail: reference also returns gate (flattened after main output).
    const int extra = out_size - NN * CH;
    if (blockIdx.x == 0 && tid < extra) out[NN * CH + tid] = gate;
}

// ---------------------------------------------------------------------------
extern "C" void kernel_launch(void* const* d_in, const int* in_sizes, int n_in,
                              void* d_out, int out_size) {
    const float* x     = (const float*)d_in[0];
    const void*  ei    = d_in[1];
    const float* W1    = (const float*)d_in[2];
    const float* b1    = (const float*)d_in[3];
    const float* W2    = (const float*)d_in[4];
    const float* b2    = (const float*)d_in[5];
    const float* alpha = (const float*)d_in[6];
    float*       out   = (float*)d_out;

    detect_k<<<1, 32>>>((const unsigned long long*)ei);

    tofp16_k<<<(NN * 32 + 255) / 256, 256>>>(
        reinterpret_cast<const float2*>(x));

    zero_k<<<(NN + 255) / 256, 256>>>();
    hist_k<<<(NE + 255) / 256, 256>>>(ei);
    scan_block_k<<<NB_SCAN, 1024>>>();
    scan_top_k<<<1, 128>>>();
    scan_add_k<<<(NN + 255) / 256, 256>>>();
    reorder_k<<<(NE + 255) / 256, 256>>>(ei);

    agg_k<<<(NN * 32 + 255) / 256, 256>>>(
        reinterpret_cast<const float2*>(x));

    static const size_t smem_bytes = SMEM_FLOATS * sizeof(float);
    cudaFuncSetAttribute(mlp_k, cudaFuncAttributeMaxDynamicSharedMemorySize,
                         (int)smem_bytes);
    mlp_k<<<592, TPB, smem_bytes>>>(W1, b1, W2, b2, alpha, out, out_size);
}

// round 11
// speedup vs baseline: 1.0848x; 1.0664x over previous
#include <cuda_runtime.h>

#define NN 100000
#define NE 1600000
#define CH 64
#define NB_SCAN 98   // ceil(NN/1024)

// Device scratch (no allocs allowed)
__device__ float g_agg[(size_t)NN * CH];     // h = x + segment_sum
__device__ int   g_cnt[NN];                  // histogram, then write cursors
__device__ int   g_off[NN];                  // exclusive offsets
__device__ int   g_blksum[128];              // scan block sums
__device__ int   g_srt[NE];                  // src ids sorted by dst
__device__ int   g_idx_is64;

// ---------------------------------------------------------------------------
// Kernel 0: detect int64-vs-int32 edge_index (JAX x64-off narrows to int32).
// ---------------------------------------------------------------------------
__global__ void detect_k(const unsigned long long* __restrict__ ei) {
    if (threadIdx.x == 0 && blockIdx.x == 0) {
        int is64 = 1;
        for (int i = 0; i < 64; i++)
            if (ei[i] >= (unsigned long long)NN) { is64 = 0; break; }
        g_idx_is64 = is64;
    }
}

__device__ __forceinline__ int load_idx(const void* eiv, long long pos) {
    if (g_idx_is64) return (int)__ldg(&((const long long*)eiv)[pos]);
    return __ldg(&((const int*)eiv)[pos]);
}

// ---------------------------------------------------------------------------
// Sort pipeline: zero -> histogram -> block scan -> top scan -> add -> reorder
// hist/reorder process 4 edges per thread (latency-bound; more MLP in flight).
// ---------------------------------------------------------------------------
__global__ void zero_k() {
    int i = blockIdx.x * blockDim.x + threadIdx.x;
    if (i < NN) g_cnt[i] = 0;
}

__global__ void hist_k(const void* __restrict__ eiv) {
    int e0 = (blockIdx.x * blockDim.x + threadIdx.x) * 4;
    if (e0 >= NE) return;
    #pragma unroll
    for (int q = 0; q < 4; q++) {
        int e = e0 + q;
        if (e < NE) atomicAdd(&g_cnt[load_idx(eiv, (long long)NE + e)], 1);
    }
}

__global__ void __launch_bounds__(1024) scan_block_k() {
    __shared__ int warp_sums[32];
    const int tid = threadIdx.x;
    const int i = blockIdx.x * 1024 + tid;
    const int lane = tid & 31, warp = tid >> 5;
    int c = (i < NN) ? g_cnt[i] : 0;
    int v = c;
    #pragma unroll
    for (int d = 1; d < 32; d <<= 1) {
        int u = __shfl_up_sync(0xffffffffu, v, d);
        if (lane >= d) v += u;
    }
    if (lane == 31) warp_sums[warp] = v;
    __syncthreads();
    if (tid < 32) {
        int w = warp_sums[tid];
        #pragma unroll
        for (int d = 1; d < 32; d <<= 1) {
            int u = __shfl_up_sync(0xffffffffu, w, d);
            if (tid >= d) w += u;
        }
        warp_sums[tid] = w;  // inclusive per-warp totals
    }
    __syncthreads();
    const int wpref = warp ? warp_sums[warp - 1] : 0;
    if (i < NN) g_off[i] = wpref + v - c;      // exclusive within block
    if (tid == 1023) g_blksum[blockIdx.x] = wpref + v;
}

__global__ void scan_top_k() {   // 1 block, 128 threads over NB_SCAN sums
    __shared__ int ws[4];
    const int tid = threadIdx.x;
    const int lane = tid & 31, warp = tid >> 5;
    int c = (tid < NB_SCAN) ? g_blksum[tid] : 0;
    int v = c;
    #pragma unroll
    for (int d = 1; d < 32; d <<= 1) {
        int u = __shfl_up_sync(0xffffffffu, v, d);
        if (lane >= d) v += u;
    }
    if (lane == 31) ws[warp] = v;
    __syncthreads();
    if (tid == 0) {
        int s = 0;
        #pragma unroll
        for (int w = 0; w < 4; w++) { int t = ws[w]; ws[w] = s; s += t; }
    }
    __syncthreads();
    if (tid < NB_SCAN) g_blksum[tid] = ws[warp] + v - c;   // exclusive
}

__global__ void scan_add_k() {
    int i = blockIdx.x * blockDim.x + threadIdx.x;
    if (i < NN) {
        int o = g_off[i] + g_blksum[i >> 10];
        g_off[i] = o;
        g_cnt[i] = o;    // running cursor for reorder
    }
}

__global__ void reorder_k(const void* __restrict__ eiv) {
    int e0 = (blockIdx.x * blockDim.x + threadIdx.x) * 4;
    if (e0 >= NE) return;
    #pragma unroll
    for (int q = 0; q < 4; q++) {
        int e = e0 + q;
        if (e < NE) {
            int src = load_idx(eiv, e);
            int dst = load_idx(eiv, (long long)NE + e);
            int pos = atomicAdd(&g_cnt[dst], 1);
            g_srt[pos] = src;
        }
    }
}

// ---------------------------------------------------------------------------
// Aggregation: one warp per node, float2 per lane. Reads sorted src list,
// accumulates in registers, writes the 256B row ONCE (no atomics).
// ---------------------------------------------------------------------------
__global__ void __launch_bounds__(256) agg_k(const float2* __restrict__ x2) {
    const int gwarp = (blockIdx.x * 256 + threadIdx.x) >> 5;
    if (gwarp >= NN) return;
    const int lane = threadIdx.x & 31;
    const int off0 = __ldg(&g_off[gwarp]);
    const int off1 = (gwarp + 1 < NN) ? __ldg(&g_off[gwarp + 1]) : NE;

    float2 acc = x2[(size_t)gwarp * 32 + lane];   // self term (eps=0 GIN)
    int j = off0;
    for (; j + 4 <= off1; j += 4) {
        int s0 = __ldg(&g_srt[j + 0]);
        int s1 = __ldg(&g_srt[j + 1]);
        int s2 = __ldg(&g_srt[j + 2]);
        int s3 = __ldg(&g_srt[j + 3]);
        float2 v0 = x2[(size_t)s0 * 32 + lane];
        float2 v1 = x2[(size_t)s1 * 32 + lane];
        float2 v2 = x2[(size_t)s2 * 32 + lane];
        float2 v3 = x2[(size_t)s3 * 32 + lane];
        acc.x += (v0.x + v1.x) + (v2.x + v3.x);
        acc.y += (v0.y + v1.y) + (v2.y + v3.y);
    }
    for (; j < off1; j++) {
        int s = __ldg(&g_srt[j]);
        float2 v = x2[(size_t)s * 32 + lane];
        acc.x += v.x; acc.y += v.y;
    }
    *reinterpret_cast<float2*>(g_agg + (size_t)gwarp * CH + lane * 2) = acc;
}

// ---------------------------------------------------------------------------
// Kernel 3: fused MLP + gate — register-blocked RPT=8.
// 256 threads = 16 j-groups x 16 r-threads; tile = 128 nodes.
// Thread (t, r) computes channels 4t..4t+3 for rows {r + 16n}, n=0..7
// (interleaved so the 2 rows sharing a warp differ by 68 floats = 4 banks
//  -> conflict-free activation LDS.128).
// Inner k-quad: 4 weight LDS.128 + 8 act LDS.128 feed 128 FMAs.
// ---------------------------------------------------------------------------
#define NPT 128       // nodes per tile
#define RPT 8         // nodes per thread
#define TPB 256
#define HS_STRIDE 68

#define SMEM_FLOATS (2 * CH * CH + 2 * CH + NPT * HS_STRIDE)

__global__ void __launch_bounds__(TPB)
mlp_k(const float* __restrict__ W1, const float* __restrict__ b1,
      const float* __restrict__ W2, const float* __restrict__ b2,
      const float* __restrict__ alpha, float* __restrict__ out,
      int out_size) {
    extern __shared__ float smem[];
    float* sW1 = smem;                       // 4096
    float* sW2 = sW1 + CH * CH;              // 4096
    float* sb1 = sW2 + CH * CH;              // 64
    float* sb2 = sb1 + CH;                   // 64
    float* hs  = sb2 + CH;                   // 128 x 68

    const int tid = threadIdx.x;
    for (int i = tid; i < CH * CH; i += TPB) {
        sW1[i] = W1[i];
        sW2[i] = W2[i];
    }
    if (tid < CH) { sb1[tid] = b1[tid]; sb2[tid] = b2[tid]; }
    const float gate = 1.0f / (1.0f + expf(-alpha[0]));
    __syncthreads();

    const int t  = tid & 15;       // j-group
    const int r  = tid >> 4;       // row lane: rows r, r+16, ..., r+112
    const int j4 = t * 4;

    for (int base = blockIdx.x * NPT; base < NN; base += gridDim.x * NPT) {
        // ---- load tile: hs[row][:] = g_agg[base+row][:]  (coalesced) ----
        for (int i = tid; i < NPT * 16; i += TPB) {
            const int row = i >> 4, g = i & 15;
            const int node = base + row;
            if (node < NN) {
                *reinterpret_cast<float4*>(&hs[row * HS_STRIDE + g * 4]) =
                    *reinterpret_cast<const float4*>(
                        g_agg + (size_t)node * CH + g * 4);
            }
        }
        __syncthreads();

        // ---- layer 1: acc = relu(h @ W1 + b1), result kept in regs ----
        float4 acc[RPT];
        {
            const float4 bb = *reinterpret_cast<const float4*>(&sb1[j4]);
            #pragma unroll
            for (int n = 0; n < RPT; n++) acc[n] = bb;
        }
        #pragma unroll
        for (int k = 0; k < CH; k += 4) {
            const float4 w0 = *reinterpret_cast<const float4*>(&sW1[(k + 0) * CH + j4]);
            const float4 w1 = *reinterpret_cast<const float4*>(&sW1[(k + 1) * CH + j4]);
            const float4 w2 = *reinterpret_cast<const float4*>(&sW1[(k + 2) * CH + j4]);
            const float4 w3 = *reinterpret_cast<const float4*>(&sW1[(k + 3) * CH + j4]);
            #pragma unroll
            for (int n = 0; n < RPT; n++) {
                const float4 a = *reinterpret_cast<const float4*>(
                    &hs[(r + 16 * n) * HS_STRIDE + k]);
                acc[n].x += a.x * w0.x + a.y * w1.x + a.z * w2.x + a.w * w3.x;
                acc[n].y += a.x * w0.y + a.y * w1.y + a.z * w2.y + a.w * w3.y;
                acc[n].z += a.x * w0.z + a.y * w1.z + a.z * w2.z + a.w * w3.z;
                acc[n].w += a.x * w0.w + a.y * w1.w + a.z * w2.w + a.w * w3.w;
            }
        }
        __syncthreads();   // everyone done reading hs
        #pragma unroll
        for (int n = 0; n < RPT; n++) {
            float4 v = acc[n];
            v.x = fmaxf(v.x, 0.0f); v.y = fmaxf(v.y, 0.0f);
            v.z = fmaxf(v.z, 0.0f); v.w = fmaxf(v.w, 0.0f);
            *reinterpret_cast<float4*>(&hs[(r + 16 * n) * HS_STRIDE + j4]) = v;
        }
        __syncthreads();

        // ---- layer 2: out = gate * (h1 @ W2 + b2) ----
        {
            const float4 bb = *reinterpret_cast<const float4*>(&sb2[j4]);
            #pragma unroll
            for (int n = 0; n < RPT; n++) acc[n] = bb;
        }
        #pragma unroll
        for (int k = 0; k < CH; k += 4) {
            const float4 w0 = *reinterpret_cast<const float4*>(&sW2[(k + 0) * CH + j4]);
            const float4 w1 = *reinterpret_cast<const float4*>(&sW2[(k + 1) * CH + j4]);
            const float4 w2 = *reinterpret_cast<const float4*>(&sW2[(k + 2) * CH + j4]);
            const float4 w3 = *reinterpret_cast<const float4*>(&sW2[(k + 3) * CH + j4]);
            #pragma unroll
            for (int n = 0; n < RPT; n++) {
                const float4 a = *reinterpret_cast<const float4*>(
                    &hs[(r + 16 * n) * HS_STRIDE + k]);
                acc[n].x += a.x * w0.x + a.y * w1.x + a.z * w2.x + a.w * w3.x;
                acc[n].y += a.x * w0.y + a.y * w1.y + a.z * w2.y + a.w * w3.y;
                acc[n].z += a.x * w0.z + a.y * w1.z + a.z * w2.z + a.w * w3.z;
                acc[n].w += a.x * w0.w + a.y * w1.w + a.z * w2.w + a.w * w3.w;
            }
        }
        #pragma unroll
        for (int n = 0; n < RPT; n++) {
            const int node = base + r + 16 * n;
            if (node < NN) {
                float4 o = make_float4(gate * acc[n].x, gate * acc[n].y,
                                       gate * acc[n].z, gate * acc[n].w);
                *reinterpret_cast<float4*>(out + (size_t)node * CH + j4) = o;
            }
        }
        __syncthreads();   // protect hs before next tile
    }

    // Tail: reference also returns gate (flattened after main output).
    const int extra = out_size - NN * CH;
    if (blockIdx.x == 0 && tid < extra) out[NN * CH + tid] = gate;
}

// ---------------------------------------------------------------------------
extern "C" void kernel_launch(void* const* d_in, const int* in_sizes, int n_in,
                              void* d_out, int out_size) {
    const float* x     = (const float*)d_in[0];
    const void*  ei    = d_in[1];
    const float* W1    = (const float*)d_in[2];
    const float* b1    = (const float*)d_in[3];
    const float* W2    = (const float*)d_in[4];
    const float* b2    = (const float*)d_in[5];
    const float* alpha = (const float*)d_in[6];
    float*       out   = (float*)d_out;

    detect_k<<<1, 32>>>((const unsigned long long*)ei);

    zero_k<<<(NN + 255) / 256, 256>>>();
    hist_k<<<(NE / 4 + 255) / 256, 256>>>(ei);
    scan_block_k<<<NB_SCAN, 1024>>>();
    scan_top_k<<<1, 128>>>();
    scan_add_k<<<(NN + 255) / 256, 256>>>();
    reorder_k<<<(NE / 4 + 255) / 256, 256>>>(ei);

    agg_k<<<(NN * 32 + 255) / 256, 256>>>(
        reinterpret_cast<const float2*>(x));

    static const size_t smem_bytes = SMEM_FLOATS * sizeof(float);
    cudaFuncSetAttribute(mlp_k, cudaFuncAttributeMaxDynamicSharedMemorySize,
                         (int)smem_bytes);
    mlp_k<<<444, TPB, smem_bytes>>>(W1, b1, W2, b2, alpha, out, out_size);
}